// round 1
// baseline (speedup 1.0000x reference)
#include <cuda_runtime.h>
#include <cuda_bf16.h>
#include <cstdint>
#include <math.h>

// Problem sizes (fixed by the reference)
#define NROW 8192   // n (pos_key / pos_value rows)
#define MROW 8192   // m (neg_value rows)
#define DDIM 256    // d

// GEMM tiling
#define BM 128
#define BN 128
#define LDS_E (DDIM + 8)   // smem row stride in bf16 elements (264) -> conflict-free ldmatrix

// Scratch (device globals: allocation-free rule)
__device__ uint4 g_pk[NROW * (DDIM / 8)];   // normalized pos_key, bf16, 512B/row
__device__ uint4 g_nv[MROW * (DDIM / 8)];   // normalized neg_value, bf16
__device__ float g_pos[NROW];               // pos_sim per row
__device__ float g_rowsum[NROW];            // sum_j exp(sim_ij / 2)

// ---------------------------------------------------------------------------
// Kernel 1: normalize rows -> bf16, compute pos_sim, zero rowsum
// grid = NROW + MROW blocks, 64 threads (one float4 per thread per row)
// ---------------------------------------------------------------------------
__global__ void __launch_bounds__(64) prep_kernel(const float4* __restrict__ pk,
                                                  const float4* __restrict__ pv,
                                                  const float4* __restrict__ nv) {
    __shared__ float sh[3][2];
    const int b = blockIdx.x;
    const int t = threadIdx.x;
    const int lane = t & 31;
    const int warp = t >> 5;

    if (b < NROW) {
        float4 k4 = pk[b * 64 + t];
        float4 v4 = pv[b * 64 + t];
        float ssk = k4.x * k4.x + k4.y * k4.y + k4.z * k4.z + k4.w * k4.w;
        float ssv = v4.x * v4.x + v4.y * v4.y + v4.z * v4.z + v4.w * v4.w;
        float dkv = k4.x * v4.x + k4.y * v4.y + k4.z * v4.z + k4.w * v4.w;
        #pragma unroll
        for (int o = 16; o > 0; o >>= 1) {
            ssk += __shfl_xor_sync(0xffffffffu, ssk, o);
            ssv += __shfl_xor_sync(0xffffffffu, ssv, o);
            dkv += __shfl_xor_sync(0xffffffffu, dkv, o);
        }
        if (lane == 0) { sh[0][warp] = ssk; sh[1][warp] = ssv; sh[2][warp] = dkv; }
        __syncthreads();
        ssk = sh[0][0] + sh[0][1];
        ssv = sh[1][0] + sh[1][1];
        dkv = sh[2][0] + sh[2][1];
        float sk = 1.0f / fmaxf(sqrtf(ssk), 1e-8f);
        float sv = 1.0f / fmaxf(sqrtf(ssv), 1e-8f);

        __nv_bfloat162 h0 = __floats2bfloat162_rn(k4.x * sk, k4.y * sk);
        __nv_bfloat162 h1 = __floats2bfloat162_rn(k4.z * sk, k4.w * sk);
        uint2 u;
        u.x = *reinterpret_cast<unsigned int*>(&h0);
        u.y = *reinterpret_cast<unsigned int*>(&h1);
        reinterpret_cast<uint2*>(g_pk)[b * 64 + t] = u;

        if (t == 0) {
            g_pos[b] = dkv * sk * sv;
            g_rowsum[b] = 0.0f;
        }
    } else {
        const int r = b - NROW;
        float4 x4 = nv[r * 64 + t];
        float ss = x4.x * x4.x + x4.y * x4.y + x4.z * x4.z + x4.w * x4.w;
        #pragma unroll
        for (int o = 16; o > 0; o >>= 1)
            ss += __shfl_xor_sync(0xffffffffu, ss, o);
        if (lane == 0) sh[0][warp] = ss;
        __syncthreads();
        ss = sh[0][0] + sh[0][1];
        float s = 1.0f / fmaxf(sqrtf(ss), 1e-8f);

        __nv_bfloat162 h0 = __floats2bfloat162_rn(x4.x * s, x4.y * s);
        __nv_bfloat162 h1 = __floats2bfloat162_rn(x4.z * s, x4.w * s);
        uint2 u;
        u.x = *reinterpret_cast<unsigned int*>(&h0);
        u.y = *reinterpret_cast<unsigned int*>(&h1);
        reinterpret_cast<uint2*>(g_nv)[r * 64 + t] = u;
    }
}

// ---------------------------------------------------------------------------
// Kernel 2: fused GEMM (pk_norm @ nv_norm^T) + exp(sim/2) row-sum
// 128x128 tile per CTA, full K=256 resident in smem, mma.sync bf16.
// 256 threads = 8 warps (2x4), warp tile 64x32.
// ---------------------------------------------------------------------------
__device__ __forceinline__ void mma16816(float* d, const uint32_t* a, const uint32_t* b) {
    asm volatile(
        "mma.sync.aligned.m16n8k16.row.col.f32.bf16.bf16.f32 "
        "{%0,%1,%2,%3},{%4,%5,%6,%7},{%8,%9},{%0,%1,%2,%3};\n"
        : "+f"(d[0]), "+f"(d[1]), "+f"(d[2]), "+f"(d[3])
        : "r"(a[0]), "r"(a[1]), "r"(a[2]), "r"(a[3]), "r"(b[0]), "r"(b[1]));
}

__global__ void __launch_bounds__(256, 1) gemm_lse_kernel() {
    extern __shared__ __nv_bfloat16 smem[];
    __nv_bfloat16* As = smem;                 // [BM][LDS_E]
    __nv_bfloat16* Bs = smem + BM * LDS_E;    // [BN][LDS_E]

    const int tid = threadIdx.x;
    const int rowblk = blockIdx.y * BM;
    const int colblk = blockIdx.x * BN;

    // ---- load A (pk) and B (nv) tiles: 128 rows x 256 bf16 each ----
    const uint4* gA = g_pk + (size_t)rowblk * (DDIM / 8);
    const uint4* gB = g_nv + (size_t)colblk * (DDIM / 8);
    #pragma unroll
    for (int i = 0; i < 16; i++) {
        int idx = tid + i * 256;          // 0..4095
        int r = idx >> 5;                 // 32 uint4 per row
        int c = idx & 31;
        *reinterpret_cast<uint4*>(As + r * LDS_E + c * 8) = gA[r * 32 + c];
        *reinterpret_cast<uint4*>(Bs + r * LDS_E + c * 8) = gB[r * 32 + c];
    }
    __syncthreads();

    const int warp = tid >> 5;
    const int lane = tid & 31;
    const int wm = (warp >> 2) * 64;   // warp row offset in tile
    const int wn = (warp & 3) * 32;    // warp col offset in tile

    float acc[4][4][4];
    #pragma unroll
    for (int mi = 0; mi < 4; mi++)
        #pragma unroll
        for (int ni = 0; ni < 4; ni++)
            #pragma unroll
            for (int c = 0; c < 4; c++)
                acc[mi][ni][c] = 0.0f;

    // ldmatrix base addresses (k column offset added per k-step, 32B per 16 elts)
    uint32_t aAddr[4], bAddr[4];
    {
        int arow = (lane & 7) + ((lane >> 3) & 1) * 8;
        int acol = (lane >> 4) * 8;
        #pragma unroll
        for (int mi = 0; mi < 4; mi++)
            aAddr[mi] = (uint32_t)__cvta_generic_to_shared(
                As + (wm + mi * 16 + arow) * LDS_E + acol);
        int brow = lane & 7;
        int bcol = ((lane >> 3) & 1) * 8;   // lanes >=16 mirror 0-15 (unused by x2)
        #pragma unroll
        for (int ni = 0; ni < 4; ni++)
            bAddr[ni] = (uint32_t)__cvta_generic_to_shared(
                Bs + (wn + ni * 8 + brow) * LDS_E + bcol);
    }

    #pragma unroll
    for (int k = 0; k < DDIM / 16; k++) {
        uint32_t a[4][4], b[4][2];
        #pragma unroll
        for (int mi = 0; mi < 4; mi++)
            asm volatile("ldmatrix.sync.aligned.m8n8.x4.shared.b16 {%0,%1,%2,%3},[%4];"
                         : "=r"(a[mi][0]), "=r"(a[mi][1]), "=r"(a[mi][2]), "=r"(a[mi][3])
                         : "r"(aAddr[mi] + k * 32));
        #pragma unroll
        for (int ni = 0; ni < 4; ni++)
            asm volatile("ldmatrix.sync.aligned.m8n8.x2.shared.b16 {%0,%1},[%2];"
                         : "=r"(b[ni][0]), "=r"(b[ni][1])
                         : "r"(bAddr[ni] + k * 32));
        #pragma unroll
        for (int mi = 0; mi < 4; mi++)
            #pragma unroll
            for (int ni = 0; ni < 4; ni++)
                mma16816(acc[mi][ni], a[mi], b[ni]);
    }
    __syncthreads();

    // ---- epilogue: rowsum of exp(sim/2) = exp2(sim * log2(e)/2) ----
    float* rowpart = reinterpret_cast<float*>(smem);
    if (tid < BM) rowpart[tid] = 0.0f;
    __syncthreads();

    const float C = 0.72134752044448170f;  // log2(e)/2
    #pragma unroll
    for (int mi = 0; mi < 4; mi++) {
        float s0 = 0.0f, s1 = 0.0f;
        #pragma unroll
        for (int ni = 0; ni < 4; ni++) {
            s0 += exp2f(acc[mi][ni][0] * C) + exp2f(acc[mi][ni][1] * C);
            s1 += exp2f(acc[mi][ni][2] * C) + exp2f(acc[mi][ni][3] * C);
        }
        s0 += __shfl_xor_sync(0xffffffffu, s0, 1);
        s0 += __shfl_xor_sync(0xffffffffu, s0, 2);
        s1 += __shfl_xor_sync(0xffffffffu, s1, 1);
        s1 += __shfl_xor_sync(0xffffffffu, s1, 2);
        if ((lane & 3) == 0) {
            int r = wm + mi * 16 + (lane >> 2);
            atomicAdd(&rowpart[r], s0);
            atomicAdd(&rowpart[r + 8], s1);
        }
    }
    __syncthreads();
    if (tid < BM) atomicAdd(&g_rowsum[rowblk + tid], rowpart[tid]);
}

// ---------------------------------------------------------------------------
// Kernel 3: final scalar reduction
// loss = mean(log(rowsum)) - 0.5 * mean(pos_sim)
// ---------------------------------------------------------------------------
__global__ void __launch_bounds__(1024) reduce_kernel(float* __restrict__ out) {
    __shared__ float sl[32], sp[32];
    const int tid = threadIdx.x;
    float ls = 0.0f, ps = 0.0f;
    for (int i = tid; i < NROW; i += 1024) {
        ls += logf(g_rowsum[i]);
        ps += g_pos[i];
    }
    #pragma unroll
    for (int o = 16; o > 0; o >>= 1) {
        ls += __shfl_xor_sync(0xffffffffu, ls, o);
        ps += __shfl_xor_sync(0xffffffffu, ps, o);
    }
    const int lane = tid & 31, warp = tid >> 5;
    if (lane == 0) { sl[warp] = ls; sp[warp] = ps; }
    __syncthreads();
    if (warp == 0) {
        ls = sl[lane];
        ps = sp[lane];
        #pragma unroll
        for (int o = 16; o > 0; o >>= 1) {
            ls += __shfl_xor_sync(0xffffffffu, ls, o);
            ps += __shfl_xor_sync(0xffffffffu, ps, o);
        }
        if (lane == 0)
            out[0] = ls * (1.0f / NROW) - 0.5f * ps * (1.0f / NROW);
    }
}

// ---------------------------------------------------------------------------
extern "C" void kernel_launch(void* const* d_in, const int* in_sizes, int n_in,
                              void* d_out, int out_size) {
    const float4* pk = reinterpret_cast<const float4*>(d_in[0]);
    const float4* pv = reinterpret_cast<const float4*>(d_in[1]);
    const float4* nv = reinterpret_cast<const float4*>(d_in[2]);
    float* out = reinterpret_cast<float*>(d_out);

    const int smem_bytes = 2 * BM * LDS_E * sizeof(__nv_bfloat16);  // 135168
    cudaFuncSetAttribute(gemm_lse_kernel,
                         cudaFuncAttributeMaxDynamicSharedMemorySize, smem_bytes);

    prep_kernel<<<NROW + MROW, 64>>>(pk, pv, nv);
    dim3 grid(MROW / BN, NROW / BM);
    gemm_lse_kernel<<<grid, 256, smem_bytes>>>();
    reduce_kernel<<<1, 1024>>>(out);
}

// round 3
// speedup vs baseline: 1.3322x; 1.3322x over previous
#include <cuda_runtime.h>
#include <cuda_bf16.h>
#include <cstdint>
#include <math.h>

#define NROW 8192
#define MROW 8192
#define DDIM 256
#define NT 32          // column tiles per CTA
#define TILE 128

// Scratch, stored PRE-SWIZZLED in 64KB blocks of 128 rows:
// block = 4 K-chunks of [128 rows x 64 bf16] (128B rows), SW128-swizzled.
__device__ uint4 g_pk[NROW * 32];   // 32 uint4 per row
__device__ uint4 g_nv[MROW * 32];
__device__ float g_pos[NROW];
__device__ float g_rowsum[NROW];

// ---------------------------------------------------------------------------
__device__ __forceinline__ uint32_t smem_u32(const void* p) {
    uint32_t a;
    asm("{ .reg .u64 t; cvta.to.shared.u64 t, %1; cvt.u32.u64 %0, t; }" : "=r"(a) : "l"(p));
    return a;
}
__device__ __forceinline__ uint32_t elect_one() {
    uint32_t p;
    asm volatile("{\n\t.reg .pred p;\n\telect.sync _|p, 0xFFFFFFFF;\n\tselp.b32 %0,1,0,p;\n\t}" : "=r"(p));
    return p;
}
__device__ __forceinline__ float ex2(float x) {
    float r;
    asm("ex2.approx.ftz.f32 %0, %1;" : "=f"(r) : "f"(x));
    return r;
}
#define MBAR_INIT(a, c) asm volatile("mbarrier.init.shared.b64 [%0], %1;" :: "r"(a), "r"(c) : "memory")
#define MBAR_EXPECT(a, n) asm volatile("mbarrier.arrive.expect_tx.shared.b64 _, [%0], %1;" :: "r"(a), "r"(n) : "memory")
#define MBAR_WAIT(a, ph) do {                                                           \
    asm volatile("{\n\t.reg .pred P1;\n\t"                                              \
                 "WL%=:\n\t"                                                            \
                 "mbarrier.try_wait.parity.acquire.cta.shared::cta.b64 P1, [%0], %1, 0x989680;\n\t" \
                 "@P1 bra.uni WD%=;\n\t"                                                \
                 "bra.uni WL%=;\n\t"                                                    \
                 "WD%=:\n\t}" :: "r"(a), "r"(ph) : "memory");                           \
} while (0)
#define BULK_LD(dst, src, bytes, mbar) asm volatile( \
    "cp.async.bulk.shared::cluster.global.mbarrier::complete_tx::bytes [%0], [%1], %2, [%3];" \
    :: "r"(dst), "l"(src), "r"(bytes), "r"(mbar) : "memory")

__device__ __forceinline__ void mma16816(float* d, const uint32_t* a, uint32_t b0, uint32_t b1) {
    asm volatile(
        "mma.sync.aligned.m16n8k16.row.col.f32.bf16.bf16.f32 "
        "{%0,%1,%2,%3},{%4,%5,%6,%7},{%8,%9},{%0,%1,%2,%3};\n"
        : "+f"(d[0]), "+f"(d[1]), "+f"(d[2]), "+f"(d[3])
        : "r"(a[0]), "r"(a[1]), "r"(a[2]), "r"(a[3]), "r"(b0), "r"(b1));
}

// ---------------------------------------------------------------------------
// Kernel 1: normalize -> bf16, write PRE-SWIZZLED tile-block layout,
// pos_sim + rowsum zero. 1 warp per row, 8 rows per block.
// Lane L owns elems [8L, 8L+8): kb = L>>3, off = rowIn*128 + (L&7)*16.
// ---------------------------------------------------------------------------
__device__ __forceinline__ void store_sw(uint4* g, int row, int lane, uint4 v) {
    int blk = row >> 7, rowIn = row & 127;
    uint32_t off = (uint32_t)(rowIn * 128 + (lane & 7) * 16);
    off = off ^ ((off >> 3) & 0x70);
    g[blk * 4096 + (lane >> 3) * 1024 + (off >> 4)] = v;
}

__global__ void __launch_bounds__(256) prep_kernel(const float4* __restrict__ pk,
                                                   const float4* __restrict__ pv,
                                                   const float4* __restrict__ nv) {
    const int row = blockIdx.x * 8 + (threadIdx.x >> 5);
    const int lane = threadIdx.x & 31;

    if (row < NROW) {
        float4 k0 = pk[row * 64 + 2 * lane], k1 = pk[row * 64 + 2 * lane + 1];
        float4 v0 = pv[row * 64 + 2 * lane], v1 = pv[row * 64 + 2 * lane + 1];
        float ssk = k0.x*k0.x + k0.y*k0.y + k0.z*k0.z + k0.w*k0.w
                  + k1.x*k1.x + k1.y*k1.y + k1.z*k1.z + k1.w*k1.w;
        float ssv = v0.x*v0.x + v0.y*v0.y + v0.z*v0.z + v0.w*v0.w
                  + v1.x*v1.x + v1.y*v1.y + v1.z*v1.z + v1.w*v1.w;
        float dkv = k0.x*v0.x + k0.y*v0.y + k0.z*v0.z + k0.w*v0.w
                  + k1.x*v1.x + k1.y*v1.y + k1.z*v1.z + k1.w*v1.w;
        #pragma unroll
        for (int o = 16; o > 0; o >>= 1) {
            ssk += __shfl_xor_sync(0xffffffffu, ssk, o);
            ssv += __shfl_xor_sync(0xffffffffu, ssv, o);
            dkv += __shfl_xor_sync(0xffffffffu, dkv, o);
        }
        float sk = 1.0f / fmaxf(sqrtf(ssk), 1e-8f);
        float sv = 1.0f / fmaxf(sqrtf(ssv), 1e-8f);
        __nv_bfloat162 h0 = __floats2bfloat162_rn(k0.x*sk, k0.y*sk);
        __nv_bfloat162 h1 = __floats2bfloat162_rn(k0.z*sk, k0.w*sk);
        __nv_bfloat162 h2 = __floats2bfloat162_rn(k1.x*sk, k1.y*sk);
        __nv_bfloat162 h3 = __floats2bfloat162_rn(k1.z*sk, k1.w*sk);
        uint4 u = make_uint4(*(unsigned*)&h0, *(unsigned*)&h1, *(unsigned*)&h2, *(unsigned*)&h3);
        store_sw(g_pk, row, lane, u);
        if (lane == 0) {
            g_pos[row] = dkv * sk * sv;
            g_rowsum[row] = 0.0f;
        }
    } else {
        const int r = row - NROW;
        float4 x0 = nv[r * 64 + 2 * lane], x1 = nv[r * 64 + 2 * lane + 1];
        float ss = x0.x*x0.x + x0.y*x0.y + x0.z*x0.z + x0.w*x0.w
                 + x1.x*x1.x + x1.y*x1.y + x1.z*x1.z + x1.w*x1.w;
        #pragma unroll
        for (int o = 16; o > 0; o >>= 1)
            ss += __shfl_xor_sync(0xffffffffu, ss, o);
        float s = 1.0f / fmaxf(sqrtf(ss), 1e-8f);
        __nv_bfloat162 h0 = __floats2bfloat162_rn(x0.x*s, x0.y*s);
        __nv_bfloat162 h1 = __floats2bfloat162_rn(x0.z*s, x0.w*s);
        __nv_bfloat162 h2 = __floats2bfloat162_rn(x1.x*s, x1.y*s);
        __nv_bfloat162 h3 = __floats2bfloat162_rn(x1.z*s, x1.w*s);
        uint4 u = make_uint4(*(unsigned*)&h0, *(unsigned*)&h1, *(unsigned*)&h2, *(unsigned*)&h3);
        store_sw(g_nv, r, lane, u);
    }
}

// ---------------------------------------------------------------------------
// Kernel 2: pipelined mma.sync GEMM + fused exp(sim/2) row-sums.
// 128 CTAs (64 rowblocks x 2 col halves), 256 thr. A (64KB) resident,
// A-frags in registers; B double-buffered via cp.async.bulk (TMA 1D).
// Warp layout: warp w owns rows [16w,16w+16), all 128 cols of the tile.
// ---------------------------------------------------------------------------
__global__ void __launch_bounds__(256, 1) gemm_lse_kernel() {
    extern __shared__ __align__(1024) char dsmem[];
    __shared__ __align__(8) uint64_t s_mbar[3];   // fullB0, fullB1, fullA

    const int tid = threadIdx.x;
    const int warp = tid >> 5;
    const int lane = tid & 31;
    const int rowblk = blockIdx.x >> 1;
    const int colhalf = blockIdx.x & 1;
    const int rowbase = rowblk * TILE;
    const int ctbase = colhalf * NT;

    uint32_t sb = smem_u32(dsmem);
    const uint32_t aBase = (sb + 1023u) & ~1023u;
    const uint32_t bBase[2] = {aBase + 65536u, aBase + 131072u};
    const uint32_t mbB[2] = {smem_u32(&s_mbar[0]), smem_u32(&s_mbar[1])};
    const uint32_t mbA = smem_u32(&s_mbar[2]);

    if (tid == 0) {
        MBAR_INIT(mbB[0], 1);
        MBAR_INIT(mbB[1], 1);
        MBAR_INIT(mbA, 1);
    }
    __syncthreads();

    if (warp == 0 && elect_one()) {
        MBAR_EXPECT(mbA, 65536u);
        BULK_LD(aBase, (const char*)g_pk + (size_t)rowblk * 65536, 65536u, mbA);
        MBAR_EXPECT(mbB[0], 65536u);
        BULK_LD(bBase[0], (const char*)g_nv + (size_t)ctbase * 65536, 65536u, mbB[0]);
    }

    // ---- load A fragments into registers (held for whole kernel) ----
    // ldmatrix.x4 per kstep: rows wm + (lane&7) + ((lane>>3)&1)*8, col (lane>>4)*16B.
    uint32_t afr[16][4];
    {
        MBAR_WAIT(mbA, 0);
        const int arow = warp * 16 + (lane & 7) + ((lane >> 3) & 1) * 8;
        const uint32_t rx = (uint32_t)((arow & 7) << 4);
        const uint32_t rb = (uint32_t)(arow * 128);
        const uint32_t lnc = (uint32_t)((lane >> 4) << 4);
        #pragma unroll
        for (int ks = 0; ks < 16; ks++) {
            uint32_t addr = aBase + ((ks >> 2) << 14) + rb + ((((uint32_t)(ks & 3) << 5) | lnc) ^ rx);
            asm volatile("ldmatrix.sync.aligned.m8n8.x4.shared.b16 {%0,%1,%2,%3},[%4];"
                         : "=r"(afr[ks][0]), "=r"(afr[ks][1]), "=r"(afr[ks][2]), "=r"(afr[ks][3])
                         : "r"(addr));
        }
    }

    // B ldmatrix per-lane address components (pair j covers n = 16j .. 16j+15)
    uint32_t brb[8], brx[8];
    {
        const int nr = (lane & 7) + ((lane >> 3) & 1) * 8;
        #pragma unroll
        for (int j = 0; j < 8; j++) {
            int r = j * 16 + nr;
            brb[j] = (uint32_t)(r * 128);
            brx[j] = (uint32_t)((r & 7) << 4) ^ (uint32_t)((lane >> 4) << 4);
        }
    }

    float acc[16][4];
    #pragma unroll
    for (int g = 0; g < 16; g++)
        #pragma unroll
        for (int c = 0; c < 4; c++) acc[g][c] = 0.0f;

    float rowacc0 = 0.0f, rowacc1 = 0.0f;
    const float C = 0.72134752044448170f;  // log2(e)/2

    for (int t = 0; t < NT; t++) {
        // backpressure: everyone done reading buf[(t+1)&1] (used at t-1)
        __syncthreads();
        if (t + 1 < NT && warp == 0 && elect_one()) {
            MBAR_EXPECT(mbB[(t + 1) & 1], 65536u);
            BULK_LD(bBase[(t + 1) & 1],
                    (const char*)g_nv + (size_t)(ctbase + t + 1) * 65536, 65536u,
                    mbB[(t + 1) & 1]);
        }
        MBAR_WAIT(mbB[t & 1], (t >> 1) & 1);

        const uint32_t bb = bBase[t & 1];
        #pragma unroll
        for (int ks = 0; ks < 16; ks++) {
            const uint32_t kch = bb + ((ks >> 2) << 14);
            const uint32_t kcol = (uint32_t)((ks & 3) << 5);
            uint32_t b[8][4];
            #pragma unroll
            for (int j = 0; j < 8; j++) {
                uint32_t addr = kch + brb[j] + (kcol ^ brx[j]);
                asm volatile("ldmatrix.sync.aligned.m8n8.x4.shared.b16 {%0,%1,%2,%3},[%4];"
                             : "=r"(b[j][0]), "=r"(b[j][1]), "=r"(b[j][2]), "=r"(b[j][3])
                             : "r"(addr));
            }
            #pragma unroll
            for (int j = 0; j < 8; j++) {
                mma16816(acc[2 * j],     afr[ks], b[j][0], b[j][2]);
                mma16816(acc[2 * j + 1], afr[ks], b[j][1], b[j][3]);
            }
        }

        // fused epilogue: rowsum += exp2(sim * log2e/2); reset acc
        float s0 = 0.0f, s1 = 0.0f;
        #pragma unroll
        for (int g = 0; g < 16; g++) {
            s0 += ex2(acc[g][0] * C) + ex2(acc[g][1] * C);
            s1 += ex2(acc[g][2] * C) + ex2(acc[g][3] * C);
            acc[g][0] = 0.0f; acc[g][1] = 0.0f; acc[g][2] = 0.0f; acc[g][3] = 0.0f;
        }
        rowacc0 += s0;
        rowacc1 += s1;
    }

    // reduce across the 4 lanes sharing a row, then one global atomic per row
    rowacc0 += __shfl_xor_sync(0xffffffffu, rowacc0, 1);
    rowacc0 += __shfl_xor_sync(0xffffffffu, rowacc0, 2);
    rowacc1 += __shfl_xor_sync(0xffffffffu, rowacc1, 1);
    rowacc1 += __shfl_xor_sync(0xffffffffu, rowacc1, 2);
    if ((lane & 3) == 0) {
        int r = rowbase + warp * 16 + (lane >> 2);
        atomicAdd(&g_rowsum[r], rowacc0);
        atomicAdd(&g_rowsum[r + 8], rowacc1);
    }
}

// ---------------------------------------------------------------------------
// Kernel 3: loss = mean(log(rowsum)) - 0.5 * mean(pos_sim)
// ---------------------------------------------------------------------------
__global__ void __launch_bounds__(1024) reduce_kernel(float* __restrict__ out) {
    __shared__ float sl[32], sp[32];
    const int tid = threadIdx.x;
    float ls = 0.0f, ps = 0.0f;
    for (int i = tid; i < NROW; i += 1024) {
        ls += logf(g_rowsum[i]);
        ps += g_pos[i];
    }
    #pragma unroll
    for (int o = 16; o > 0; o >>= 1) {
        ls += __shfl_xor_sync(0xffffffffu, ls, o);
        ps += __shfl_xor_sync(0xffffffffu, ps, o);
    }
    const int lane = tid & 31, warp = tid >> 5;
    if (lane == 0) { sl[warp] = ls; sp[warp] = ps; }
    __syncthreads();
    if (warp == 0) {
        ls = sl[lane];
        ps = sp[lane];
        #pragma unroll
        for (int o = 16; o > 0; o >>= 1) {
            ls += __shfl_xor_sync(0xffffffffu, ls, o);
            ps += __shfl_xor_sync(0xffffffffu, ps, o);
        }
        if (lane == 0)
            out[0] = ls * (1.0f / NROW) - 0.5f * ps * (1.0f / NROW);
    }
}

// ---------------------------------------------------------------------------
extern "C" void kernel_launch(void* const* d_in, const int* in_sizes, int n_in,
                              void* d_out, int out_size) {
    const float4* pk = reinterpret_cast<const float4*>(d_in[0]);
    const float4* pv = reinterpret_cast<const float4*>(d_in[1]);
    const float4* nv = reinterpret_cast<const float4*>(d_in[2]);
    float* out = reinterpret_cast<float*>(d_out);

    const int smem_bytes = 1024 + 3 * 65536;  // pad + A + 2x B
    cudaFuncSetAttribute(gemm_lse_kernel,
                         cudaFuncAttributeMaxDynamicSharedMemorySize, smem_bytes);

    prep_kernel<<<(NROW + MROW) / 8, 256>>>(pk, pv, nv);
    gemm_lse_kernel<<<128, 256, smem_bytes>>>();
    reduce_kernel<<<1, 1024>>>(out);
}